// round 1
// baseline (speedup 1.0000x reference)
#include <cuda_runtime.h>
#include <cuda_bf16.h>
#include <cstdint>

// Problem constants
#define BB 8
#define SS 4096           // WIDTH*WIDTH
#define EE 128
#define WIDTH 64
#define NEDGE 512         // 32 paths * 16 edges per batch

// Scratch for hidden = A @ v  (16 MB, static device allocation — allowed)
__device__ float g_hidden[(size_t)BB * SS * EE];

// ---------------------------------------------------------------------------
// Fill attn region with bp broadcast: out[row*128 + e] = bp[e]
// grid covers B*S*32 float4 stores
__global__ void fill_bp_kernel(float4* __restrict__ out, const float4* __restrict__ bp4) {
    unsigned tid = blockIdx.x * blockDim.x + threadIdx.x;   // 0 .. B*S*32-1
    out[tid] = bp4[tid & 31];
}

// ---------------------------------------------------------------------------
// Scatter adjacency ones into both A copies.
// edges: [B, 512, 2, 2] int32, last dim = (x, y); node = y*WIDTH + x
__global__ void set_edges_kernel(float* __restrict__ A1, float* __restrict__ A2,
                                 const int* __restrict__ edges) {
    int b = blockIdx.x;
    int i = threadIdx.x;           // 0..511
    const int* e = edges + ((size_t)b * NEDGE + i) * 4;
    int src = e[1] * WIDTH + e[0];
    int dst = e[3] * WIDTH + e[2];
    size_t off = (size_t)b * SS * SS + (size_t)src * SS + dst;
    A1[off] = 1.0f;
    A2[off] = 1.0f;
}

// ---------------------------------------------------------------------------
// Per unique edge (b, src, dst): hidden[b,src,:] += values[b,dst,:] @ Wv + bv
// One block (128 threads) per edge. Dedupe against earlier edges of the batch
// (A was built with .set(1.0), so duplicate edges count once).
__global__ void accum_hidden_kernel(const float* __restrict__ values,
                                    const float* __restrict__ Wv,
                                    const float* __restrict__ bv,
                                    const int* __restrict__ edges) {
    int b = blockIdx.y;
    int i = blockIdx.x;            // edge index 0..511
    const int* eb = edges + (size_t)b * NEDGE * 4;
    int src = eb[i * 4 + 1] * WIDTH + eb[i * 4 + 0];
    int dst = eb[i * 4 + 3] * WIDTH + eb[i * 4 + 2];
    int key = src * SS + dst;

    __shared__ int dup;
    if (threadIdx.x == 0) dup = 0;
    __syncthreads();
    for (int j = threadIdx.x; j < i; j += blockDim.x) {
        int s2 = eb[j * 4 + 1] * WIDTH + eb[j * 4 + 0];
        int d2 = eb[j * 4 + 3] * WIDTH + eb[j * 4 + 2];
        if (s2 * SS + d2 == key) dup = 1;   // benign race
    }
    __syncthreads();
    if (dup) return;

    __shared__ float vrow[EE];
    int e = threadIdx.x;
    vrow[e] = values[((size_t)b * SS + dst) * EE + e];
    __syncthreads();

    float acc = bv[e];
    #pragma unroll 16
    for (int k = 0; k < EE; k++) {
        acc = fmaf(vrow[k], Wv[k * EE + e], acc);
    }
    atomicAdd(&g_hidden[((size_t)b * SS + src) * EE + e], acc);
}

// ---------------------------------------------------------------------------
// For each edge src row: attn[b,src,:] = hidden[b,src,:] @ Wp + bp
// Duplicate src rows write identical values — benign.
__global__ void out_rows_kernel(float* __restrict__ attn,
                                const float* __restrict__ Wp,
                                const float* __restrict__ bp,
                                const int* __restrict__ edges) {
    int b = blockIdx.y;
    int i = blockIdx.x;
    const int* eb = edges + ((size_t)b * NEDGE + i) * 4;
    int src = eb[1] * WIDTH + eb[0];

    __shared__ float hrow[EE];
    int e = threadIdx.x;
    hrow[e] = g_hidden[((size_t)b * SS + src) * EE + e];
    __syncthreads();

    float acc = bp[e];
    #pragma unroll 16
    for (int k = 0; k < EE; k++) {
        acc = fmaf(hrow[k], Wp[k * EE + e], acc);
    }
    attn[((size_t)b * SS + src) * EE + e] = acc;
}

// ---------------------------------------------------------------------------
extern "C" void kernel_launch(void* const* d_in, const int* in_sizes, int n_in,
                              void* d_out, int out_size) {
    (void)in_sizes; (void)n_in; (void)out_size;

    // Input order (metadata): queries, keys, values, oracle_edges,
    //                          Wq, bq, Wk, bk, Wv, bv, Wp, bp
    const float* values = (const float*)d_in[2];
    const int*   edges  = (const int*)  d_in[3];
    const float* Wv     = (const float*)d_in[8];
    const float* bv     = (const float*)d_in[9];
    const float* Wp     = (const float*)d_in[10];
    const float* bp     = (const float*)d_in[11];

    float* out  = (float*)d_out;
    float* attn = out;                                    // [B,S,E]
    float* A1   = out + (size_t)BB * SS * EE;             // [B,S,S]
    float* A2   = A1 + (size_t)BB * SS * SS;              // [B,S,S]

    // Zero both adjacency copies (contiguous 1.07 GB) — memset node, full HBM BW
    cudaMemsetAsync(A1, 0, 2ull * BB * SS * SS * sizeof(float));

    // Zero hidden scratch (16 MB)
    void* hidden_ptr = nullptr;
    cudaGetSymbolAddress(&hidden_ptr, g_hidden);
    cudaMemsetAsync(hidden_ptr, 0, (size_t)BB * SS * EE * sizeof(float));

    // attn := bp broadcast  (B*S*32 float4 stores)
    {
        unsigned total4 = BB * SS * (EE / 4);             // 1,048,576
        fill_bp_kernel<<<total4 / 256, 256>>>((float4*)attn, (const float4*)bp);
    }

    // A[b,src,dst] = 1  (both copies)
    set_edges_kernel<<<BB, NEDGE>>>(A1, A2, edges);

    // hidden accumulation (deduped)
    {
        dim3 grid(NEDGE, BB);
        accum_hidden_kernel<<<grid, EE>>>(values, Wv, bv, edges);
    }

    // overwrite touched attn rows with hidden @ Wp + bp
    {
        dim3 grid(NEDGE, BB);
        out_rows_kernel<<<grid, EE>>>(attn, Wp, bp, edges);
    }
}